// round 13
// baseline (speedup 1.0000x reference)
#include <cuda_runtime.h>
#include <cuda_fp16.h>
#include <cstdint>

#define N_NODES 50000
#define N_PAD   50048            // 391 * 128
#define D 128
#define R 8
#define E_PER 80000
#define NB 4
#define NF 4
#define V 1000
#define OUT 16
#define NKEYS (R * N_NODES)      // 400000
#define NEDGE (R * E_PER)        // 640000
#define KDIM 640                 // 4*128 (M_b) + 128 (x)

#define SCAN_B 1024
#define SCAN_ITEMS 4
#define SCAN_TILE (SCAN_B * SCAN_ITEMS)
#define SCAN_NBLK ((NKEYS + SCAN_TILE - 1) / SCAN_TILE)   // 98

// ---------------- scratch (device globals; no allocation allowed) ----------
__device__ __align__(16) __half g_Af[(size_t)N_PAD * KDIM];   // A, single fp16
__device__ __align__(16) __half g_Bf[D * KDIM];               // B^T, single fp16
__device__ int   g_counts[NKEYS];
__device__ int   g_offsets[NKEYS];
__device__ int   g_cursor[NKEYS];
__device__ int   g_partials[128];
__device__ int   g_csr_src[NEDGE];
__device__ float g_biasH[D];

// ======================= PTX helpers (sm_80+ features only) =================
__device__ __forceinline__ uint32_t smem_u32(const void* p) {
    uint32_t a;
    asm("{ .reg .u64 t; cvta.to.shared.u64 t, %1; cvt.u32.u64 %0, t; }" : "=r"(a) : "l"(p));
    return a;
}
#define CP_ASYNC16(saddr, gaddr) \
    asm volatile("cp.async.cg.shared.global [%0], [%1], 16;" :: "r"(saddr), "l"(gaddr))
#define CP_COMMIT() asm volatile("cp.async.commit_group;" ::: "memory")
#define CP_WAIT(n)  asm volatile("cp.async.wait_group %0;" :: "n"(n) : "memory")

#define LDSM4(r, addr) \
    asm volatile("ldmatrix.sync.aligned.m8n8.x4.shared.b16 {%0,%1,%2,%3}, [%4];" \
        : "=r"((r)[0]), "=r"((r)[1]), "=r"((r)[2]), "=r"((r)[3]) : "r"(addr))

#define MMA16816F16(c, a, b) \
    asm volatile("mma.sync.aligned.m16n8k16.row.col.f32.f16.f16.f32 " \
        "{%0,%1,%2,%3}, {%4,%5,%6,%7}, {%8,%9}, {%0,%1,%2,%3};" \
        : "+f"((c)[0]), "+f"((c)[1]), "+f"((c)[2]), "+f"((c)[3]) \
        : "r"((a)[0]), "r"((a)[1]), "r"((a)[2]), "r"((a)[3]), \
          "r"((b)[0]), "r"((b)[1]))

// write float4 as 4 fp16 (8B packed store)
__device__ __forceinline__ void store_h4(float4 v, __half* p) {
    __half2 a = __floats2half2_rn(v.x, v.y);
    __half2 b = __floats2half2_rn(v.z, v.w);
    uint2 u;
    u.x = *reinterpret_cast<unsigned*>(&a);
    u.y = *reinterpret_cast<unsigned*>(&b);
    *reinterpret_cast<uint2*>(p) = u;
}

// ---------------- zero counts ----------------------------------------------
__global__ void k_zero() {
    int i = blockIdx.x * blockDim.x + threadIdx.x;
    if (i < NKEYS) g_counts[i] = 0;
}

// ---------------- x = sum_f emb[f, codes[f, nid[n]]]  (fp16 into A) ---------
__global__ void k_gather_x(const int* __restrict__ fc, const int* __restrict__ nid,
                           const float* __restrict__ emb) {
    int w = (blockIdx.x * blockDim.x + threadIdx.x) >> 5;
    int lane = threadIdx.x & 31;
    if (w >= N_NODES) return;
    int node = nid[w];
    float4 acc = make_float4(0.f, 0.f, 0.f, 0.f);
#pragma unroll
    for (int f = 0; f < NF; f++) {
        int code = fc[f * N_NODES + node];
        const float4* src = (const float4*)(emb + ((size_t)f * V + code) * D);
        float4 v = src[lane];
        acc.x += v.x; acc.y += v.y; acc.z += v.z; acc.w += v.w;
    }
    store_h4(acc, g_Af + (size_t)w * KDIM + 512 + lane * 4);
}

// ---------------- B^T fp16 + biasH -------------------------------------------
__global__ void k_prepB(const float* __restrict__ basis, const float* __restrict__ W_self,
                        const float* __restrict__ b_rel, const float* __restrict__ h_bias) {
    int idx = blockIdx.x * blockDim.x + threadIdx.x;
    if (idx < D) {
        float s = h_bias[idx];
#pragma unroll
        for (int r = 0; r < R; r++) s += b_rel[r * D + idx];
        g_biasH[idx] = s;
    }
    if (idx >= D * KDIM) return;
    int n = idx / KDIM;
    int k = idx % KDIM;
    float v;
    if (k < 512) {
        v = basis[(size_t)((k >> 7) * D + (k & 127)) * D + n];
    } else {
        v = 0.f;
#pragma unroll
        for (int r = 0; r < R; r++) v += W_self[(size_t)(r * D + (k - 512)) * D + n];
    }
    g_Bf[idx] = __float2half_rn(v);
}

// ---------------- CSR build: count -> scan (2 kernels) -> fill ---------------
__global__ void k_count(const int* __restrict__ edst) {
    int i = blockIdx.x * blockDim.x + threadIdx.x;
    if (i >= NEDGE) return;
    int r = i / E_PER;
    atomicAdd(&g_counts[r * N_NODES + edst[i]], 1);
}

__global__ void k_scan1() {
    __shared__ int s[SCAN_B];
    int tid = threadIdx.x;
    int base = blockIdx.x * SCAN_TILE + tid * SCAN_ITEMS;
    int local[SCAN_ITEMS];
    int tsum = 0;
#pragma unroll
    for (int q = 0; q < SCAN_ITEMS; q++) {
        int idx = base + q;
        local[q] = (idx < NKEYS) ? g_counts[idx] : 0;
        tsum += local[q];
    }
    s[tid] = tsum;
    __syncthreads();
    for (int off = 1; off < SCAN_B; off <<= 1) {
        int v = 0;
        if (tid >= off) v = s[tid - off];
        __syncthreads();
        s[tid] += v;
        __syncthreads();
    }
    int run = s[tid] - tsum;
#pragma unroll
    for (int q = 0; q < SCAN_ITEMS; q++) {
        int idx = base + q;
        if (idx < NKEYS) g_offsets[idx] = run;
        run += local[q];
    }
    if (tid == SCAN_B - 1) g_partials[blockIdx.x] = s[tid];
}

// scan3: each block redundantly reduces the preceding blocks' partials
// (98 values) — eliminates the separate single-block scan2 kernel.
__global__ void k_scan3() {
    __shared__ int sp[128];
    int tid = threadIdx.x;
    if (tid < 128) sp[tid] = (tid < (int)blockIdx.x && tid < SCAN_NBLK) ? g_partials[tid] : 0;
    __syncthreads();
#pragma unroll
    for (int off = 64; off > 0; off >>= 1) {
        if (tid < off) sp[tid] += sp[tid + off];
        __syncthreads();
    }
    int add = sp[0];
    int base = blockIdx.x * SCAN_TILE;
#pragma unroll
    for (int q = 0; q < SCAN_ITEMS; q++) {
        int idx = base + tid + q * SCAN_B;
        if (idx < NKEYS) {
            int v = g_offsets[idx] + add;
            g_offsets[idx] = v;
            g_cursor[idx] = v;
        }
    }
}

__global__ void k_fill(const int* __restrict__ esrc, const int* __restrict__ edst) {
    int i = blockIdx.x * blockDim.x + threadIdx.x;
    if (i >= NEDGE) return;
    int r = i / E_PER;
    int key = r * N_NODES + edst[i];
    int pos = atomicAdd(&g_cursor[key], 1);
    g_csr_src[pos] = esrc[i];
}

// ---------------- M_b accumulation (warp per node; high-MLP index fetch) -----
// Hoists (cnt,start) for all 8 relations, lane-parallel fetches each relation's
// source indices (coalesced), shfl-broadcasts them — row-gather addresses come
// from registers, not a dependent L2 load. Accumulation order unchanged.
__global__ void k_edge(const float* __restrict__ coeff) {
    int w = (blockIdx.x * blockDim.x + threadIdx.x) >> 5;
    int lane = threadIdx.x & 31;
    if (w >= N_NODES) return;

    int cnts[R], starts[R], mysrc[R];
#pragma unroll
    for (int r = 0; r < R; r++) {
        int key = r * N_NODES + w;
        cnts[r]   = g_counts[key];
        starts[r] = g_offsets[key];
    }
#pragma unroll
    for (int r = 0; r < R; r++)
        mysrc[r] = (lane < cnts[r]) ? g_csr_src[starts[r] + lane] : 0;

    float4 macc[NB];
#pragma unroll
    for (int b = 0; b < NB; b++) macc[b] = make_float4(0.f, 0.f, 0.f, 0.f);

#pragma unroll
    for (int r = 0; r < R; r++) {
        int cnt = cnts[r];
        float4 ms = make_float4(0.f, 0.f, 0.f, 0.f);
        int lim = min(cnt, 32);
        for (int e = 0; e < lim; e++) {
            int s = __shfl_sync(0xFFFFFFFFu, mysrc[r], e);
            uint2 u = ((const uint2*)(g_Af + (size_t)s * KDIM + 512))[lane];
            float2 f01 = __half22float2(*reinterpret_cast<__half2*>(&u.x));
            float2 f23 = __half22float2(*reinterpret_cast<__half2*>(&u.y));
            ms.x += f01.x; ms.y += f01.y; ms.z += f23.x; ms.w += f23.y;
        }
        for (int e = 32; e < cnt; e++) {          // safety fallback (never taken here)
            int s = g_csr_src[starts[r] + e];
            uint2 u = ((const uint2*)(g_Af + (size_t)s * KDIM + 512))[lane];
            float2 f01 = __half22float2(*reinterpret_cast<__half2*>(&u.x));
            float2 f23 = __half22float2(*reinterpret_cast<__half2*>(&u.y));
            ms.x += f01.x; ms.y += f01.y; ms.z += f23.x; ms.w += f23.y;
        }
        float inv = 1.0f / fmaxf((float)cnt, 1.0f);
#pragma unroll
        for (int b = 0; b < NB; b++) {
            float c = coeff[r * NB + b] * inv;
            macc[b].x += c * ms.x;
            macc[b].y += c * ms.y;
            macc[b].z += c * ms.z;
            macc[b].w += c * ms.w;
        }
    }
#pragma unroll
    for (int b = 0; b < NB; b++)
        store_h4(macc[b], g_Af + (size_t)w * KDIM + b * D + lane * 4);
}

// ---------------- mma.sync GEMM + fused bias/ReLU/logits epilogue ------------
// CTA: 128x128, 512 threads, 16 warps (4x4), warp tile 32x32.
// BK=64 per stage, double-buffered cp.async.
// D = A*B (both single fp16). __launch_bounds__(512,2) for 2-CTA co-residency.
#define BK 64
#define NSTAGE 10                 // KDIM / BK
#define SAS 144                   // smem row stride bytes (128B data + 16B pad)
#define TILE_B (128 * SAS)        // 18432 per matrix
#define OFF_A  0
#define OFF_B  (1 * TILE_B)
#define STAGE_B (2 * TILE_B)      // 36864
#define OFF_WC   (2 * STAGE_B)    // 73728
#define OFF_BIAS (OFF_WC + 8192)
#define OFF_BCLS (OFF_BIAS + 512)
#define SM_TOTAL (OFF_BCLS + 128) // 82560 (staging 128x132 f32 reuses tile area)
#define STG_STRIDE 132

__global__ void __launch_bounds__(512, 2) k_gemm_mma(const float* __restrict__ W_cls,
                                                     const float* __restrict__ b_cls,
                                                     float* __restrict__ out) {
    extern __shared__ char smem[];
    uint32_t sb = smem_u32(smem);
    int tid = threadIdx.x;
    int lane = tid & 31, wid = tid >> 5;
    int wm = wid & 3, wn = wid >> 2;          // warp tile at (wm*32, wn*32)
    int n0 = blockIdx.x * 128;

    float* sWc   = (float*)(smem + OFF_WC);
    float* sBias = (float*)(smem + OFF_BIAS);
    float* sBcls = (float*)(smem + OFF_BCLS);
    for (int i = tid; i < D * OUT; i += 512) sWc[i] = W_cls[i];
    if (tid < D)   sBias[tid] = g_biasH[tid];
    if (tid < OUT) sBcls[tid] = b_cls[tid];

    float acc[2][4][4];
#pragma unroll
    for (int mt = 0; mt < 2; mt++)
#pragma unroll
        for (int nt = 0; nt < 4; nt++)
#pragma unroll
            for (int q = 0; q < 4; q++) acc[mt][nt][q] = 0.f;

    // 512 threads: 2 x 16B chunks per matrix per thread per stage (BK=64 = 128B/row).
    auto load_stage = [&](int s) {
        uint32_t sm0 = sb + (s & 1) * STAGE_B;
        int k0 = s * BK;
        int row = tid >> 2, kc = tid & 3;     // 128 rows x 4 chunk-pairs
        uint32_t soff = row * SAS + kc * 16;
        size_t aoff = (size_t)(n0 + row) * KDIM + k0 + kc * 8;
        size_t boff = (size_t)row * KDIM + k0 + kc * 8;
        CP_ASYNC16(sm0 + OFF_A + soff,      g_Af + aoff);
        CP_ASYNC16(sm0 + OFF_A + soff + 64, g_Af + aoff + 32);
        CP_ASYNC16(sm0 + OFF_B + soff,      g_Bf + boff);
        CP_ASYNC16(sm0 + OFF_B + soff + 64, g_Bf + boff + 32);
    };

    load_stage(0); CP_COMMIT();

    for (int s = 0; s < NSTAGE; s++) {
        if (s + 1 < NSTAGE) {
            load_stage(s + 1); CP_COMMIT();
            CP_WAIT(1);
        } else {
            CP_WAIT(0);
        }
        __syncthreads();

        uint32_t base = sb + (s & 1) * STAGE_B;
#pragma unroll
        for (int ks = 0; ks < 4; ks++) {
            uint32_t a[2][4], b[4][2];
#pragma unroll
            for (int mt = 0; mt < 2; mt++) {
                uint32_t ro = (uint32_t)(wm * 32 + mt * 16 + (lane & 15)) * SAS
                              + ks * 32 + ((lane >> 4) << 4);
                LDSM4(a[mt], base + OFF_A + ro);
            }
#pragma unroll
            for (int ntp = 0; ntp < 2; ntp++) {
                uint32_t ro = (uint32_t)(wn * 32 + ntp * 16 + ((lane >> 4) << 3) + (lane & 7)) * SAS
                              + ks * 32 + (((lane >> 3) & 1) << 4);
                uint32_t t[4];
                LDSM4(t, base + OFF_B + ro);
                b[2 * ntp][0] = t[0]; b[2 * ntp][1] = t[1];
                b[2 * ntp + 1][0] = t[2]; b[2 * ntp + 1][1] = t[3];
            }
#pragma unroll
            for (int mt = 0; mt < 2; mt++)
#pragma unroll
                for (int nt = 0; nt < 4; nt++)
                    MMA16816F16(acc[mt][nt], a[mt], b[nt]);
        }
        __syncthreads();
    }

    // -------- epilogue: bias + relu into staging smem --------
    float* stg = (float*)smem;                 // 128 x 132, reuses tile area
#pragma unroll
    for (int mt = 0; mt < 2; mt++) {
        int rl0 = wm * 32 + mt * 16 + (lane >> 2);
#pragma unroll
        for (int nt = 0; nt < 4; nt++) {
            int col0 = wn * 32 + nt * 8 + (lane & 3) * 2;
            stg[(rl0)     * STG_STRIDE + col0    ] = fmaxf(acc[mt][nt][0] + sBias[col0],     0.f);
            stg[(rl0)     * STG_STRIDE + col0 + 1] = fmaxf(acc[mt][nt][1] + sBias[col0 + 1], 0.f);
            stg[(rl0 + 8) * STG_STRIDE + col0    ] = fmaxf(acc[mt][nt][2] + sBias[col0],     0.f);
            stg[(rl0 + 8) * STG_STRIDE + col0 + 1] = fmaxf(acc[mt][nt][3] + sBias[col0 + 1], 0.f);
        }
    }
    __syncthreads();

    // -------- per-row: store h + compute logits --------
    if (tid < 128) {
        int node = n0 + tid;
        if (node < N_NODES) {
            float a[OUT];
#pragma unroll
            for (int o = 0; o < OUT; o++) a[o] = sBcls[o];
            const float4* row = (const float4*)(stg + tid * STG_STRIDE);
            float* hptr = out + (size_t)N_NODES * OUT + (size_t)node * D;
#pragma unroll
            for (int q = 0; q < 32; q++) {
                float4 v = row[q];
                const float* w0 = sWc + (q * 4) * OUT;
#pragma unroll
                for (int o = 0; o < OUT; o++)
                    a[o] += v.x * w0[o] + v.y * w0[OUT + o]
                          + v.z * w0[2 * OUT + o] + v.w * w0[3 * OUT + o];
                ((float4*)hptr)[q] = v;
            }
            float* lptr = out + (size_t)node * OUT;
#pragma unroll
            for (int q = 0; q < 4; q++) {
                float4 v;
                v.x = a[q * 4]; v.y = a[q * 4 + 1]; v.z = a[q * 4 + 2]; v.w = a[q * 4 + 3];
                ((float4*)lptr)[q] = v;
            }
        }
    }
}

// ---------------- launch (fork-join: gather/prepB overlap the CSR chain) -----
extern "C" void kernel_launch(void* const* d_in, const int* in_sizes, int n_in,
                              void* d_out, int out_size) {
    const int*   feat_codes = (const int*)d_in[0];
    const int*   nid        = (const int*)d_in[1];
    const int*   esrc       = (const int*)d_in[2];
    const int*   edst       = (const int*)d_in[3];
    const float* emb        = (const float*)d_in[4];
    const float* basis      = (const float*)d_in[5];
    const float* coeff      = (const float*)d_in[6];
    const float* W_self     = (const float*)d_in[7];
    const float* b_rel      = (const float*)d_in[8];
    const float* h_bias     = (const float*)d_in[9];
    const float* W_cls      = (const float*)d_in[10];
    const float* b_cls      = (const float*)d_in[11];
    float* out = (float*)d_out;

    static cudaStream_t s2 = nullptr;
    static cudaEvent_t evFork = nullptr, evJoin = nullptr;
    if (s2 == nullptr) {
        cudaFuncSetAttribute(k_gemm_mma, cudaFuncAttributeMaxDynamicSharedMemorySize, SM_TOTAL);
        cudaStreamCreateWithFlags(&s2, cudaStreamNonBlocking);
        cudaEventCreateWithFlags(&evFork, cudaEventDisableTiming);
        cudaEventCreateWithFlags(&evJoin, cudaEventDisableTiming);
    }

    // fork: side stream runs gather_x + prepB concurrently with the CSR chain
    cudaEventRecord(evFork, 0);
    cudaStreamWaitEvent(s2, evFork, 0);
    k_gather_x<<<(N_NODES + 7) / 8, 256, 0, s2>>>(feat_codes, nid, emb);
    k_prepB<<<(D * KDIM + 255) / 256, 256, 0, s2>>>(basis, W_self, b_rel, h_bias);
    cudaEventRecord(evJoin, s2);

    // main (capture) stream: CSR build
    k_zero<<<(NKEYS + 1023) / 1024, 1024>>>();
    k_count<<<(NEDGE + 255) / 256, 256>>>(edst);
    k_scan1<<<SCAN_NBLK, SCAN_B>>>();
    k_scan3<<<SCAN_NBLK, SCAN_B>>>();
    k_fill<<<(NEDGE + 255) / 256, 256>>>(esrc, edst);

    // join: edge gather needs both branches
    cudaStreamWaitEvent(0, evJoin, 0);
    k_edge<<<(N_NODES + 7) / 8, 256>>>(coeff);
    k_gemm_mma<<<N_PAD / 128, 512, SM_TOTAL>>>(W_cls, b_cls, out);
}

// round 14
// speedup vs baseline: 1.2356x; 1.2356x over previous
#include <cuda_runtime.h>
#include <cuda_fp16.h>
#include <cstdint>

#define N_NODES 50000
#define N_PAD   50048            // 391 * 128
#define D 128
#define R 8
#define E_PER 80000
#define NB 4
#define NF 4
#define V 1000
#define OUT 16
#define NKEYS (R * N_NODES)      // 400000
#define NEDGE (R * E_PER)        // 640000
#define KDIM 640                 // 4*128 (M_b) + 128 (x)

#define SCAN_B 1024
#define SCAN_ITEMS 4
#define SCAN_TILE (SCAN_B * SCAN_ITEMS)
#define SCAN_NBLK ((NKEYS + SCAN_TILE - 1) / SCAN_TILE)   // 98

// ---------------- scratch (device globals; no allocation allowed) ----------
__device__ __align__(16) __half g_Af[(size_t)N_PAD * KDIM];   // A, single fp16
__device__ __align__(16) __half g_Bf[D * KDIM];               // B^T, single fp16
__device__ int   g_counts[NKEYS];
__device__ int   g_offsets[NKEYS];
__device__ int   g_cursor[NKEYS];
__device__ int   g_partials[128];
__device__ int   g_csr_src[NEDGE];
__device__ float g_biasH[D];

// ======================= PTX helpers (sm_80+ features only) =================
__device__ __forceinline__ uint32_t smem_u32(const void* p) {
    uint32_t a;
    asm("{ .reg .u64 t; cvta.to.shared.u64 t, %1; cvt.u32.u64 %0, t; }" : "=r"(a) : "l"(p));
    return a;
}
#define CP_ASYNC16(saddr, gaddr) \
    asm volatile("cp.async.cg.shared.global [%0], [%1], 16;" :: "r"(saddr), "l"(gaddr))
#define CP_COMMIT() asm volatile("cp.async.commit_group;" ::: "memory")
#define CP_WAIT(n)  asm volatile("cp.async.wait_group %0;" :: "n"(n) : "memory")

#define LDSM4(r, addr) \
    asm volatile("ldmatrix.sync.aligned.m8n8.x4.shared.b16 {%0,%1,%2,%3}, [%4];" \
        : "=r"((r)[0]), "=r"((r)[1]), "=r"((r)[2]), "=r"((r)[3]) : "r"(addr))

#define MMA16816F16(c, a, b) \
    asm volatile("mma.sync.aligned.m16n8k16.row.col.f32.f16.f16.f32 " \
        "{%0,%1,%2,%3}, {%4,%5,%6,%7}, {%8,%9}, {%0,%1,%2,%3};" \
        : "+f"((c)[0]), "+f"((c)[1]), "+f"((c)[2]), "+f"((c)[3]) \
        : "r"((a)[0]), "r"((a)[1]), "r"((a)[2]), "r"((a)[3]), \
          "r"((b)[0]), "r"((b)[1]))

// write float4 as 4 fp16 (8B packed store)
__device__ __forceinline__ void store_h4(float4 v, __half* p) {
    __half2 a = __floats2half2_rn(v.x, v.y);
    __half2 b = __floats2half2_rn(v.z, v.w);
    uint2 u;
    u.x = *reinterpret_cast<unsigned*>(&a);
    u.y = *reinterpret_cast<unsigned*>(&b);
    *reinterpret_cast<uint2*>(p) = u;
}

// ---------------- zero counts ----------------------------------------------
__global__ void k_zero() {
    int i = blockIdx.x * blockDim.x + threadIdx.x;
    if (i < NKEYS) g_counts[i] = 0;
}

// ---------------- x = sum_f emb[f, codes[f, nid[n]]]  (fp16 into A) ---------
__global__ void k_gather_x(const int* __restrict__ fc, const int* __restrict__ nid,
                           const float* __restrict__ emb) {
    int w = (blockIdx.x * blockDim.x + threadIdx.x) >> 5;
    int lane = threadIdx.x & 31;
    if (w >= N_NODES) return;
    int node = nid[w];
    float4 acc = make_float4(0.f, 0.f, 0.f, 0.f);
#pragma unroll
    for (int f = 0; f < NF; f++) {
        int code = fc[f * N_NODES + node];
        const float4* src = (const float4*)(emb + ((size_t)f * V + code) * D);
        float4 v = src[lane];
        acc.x += v.x; acc.y += v.y; acc.z += v.z; acc.w += v.w;
    }
    store_h4(acc, g_Af + (size_t)w * KDIM + 512 + lane * 4);
}

// ---------------- B^T fp16 + biasH -------------------------------------------
__global__ void k_prepB(const float* __restrict__ basis, const float* __restrict__ W_self,
                        const float* __restrict__ b_rel, const float* __restrict__ h_bias) {
    int idx = blockIdx.x * blockDim.x + threadIdx.x;
    if (idx < D) {
        float s = h_bias[idx];
#pragma unroll
        for (int r = 0; r < R; r++) s += b_rel[r * D + idx];
        g_biasH[idx] = s;
    }
    if (idx >= D * KDIM) return;
    int n = idx / KDIM;
    int k = idx % KDIM;
    float v;
    if (k < 512) {
        v = basis[(size_t)((k >> 7) * D + (k & 127)) * D + n];
    } else {
        v = 0.f;
#pragma unroll
        for (int r = 0; r < R; r++) v += W_self[(size_t)(r * D + (k - 512)) * D + n];
    }
    g_Bf[idx] = __float2half_rn(v);
}

// ---------------- CSR build: count -> scan -> fill --------------------------
__global__ void k_count(const int* __restrict__ edst) {
    int i = blockIdx.x * blockDim.x + threadIdx.x;
    if (i >= NEDGE) return;
    int r = i / E_PER;
    atomicAdd(&g_counts[r * N_NODES + edst[i]], 1);
}

__global__ void k_scan1() {
    __shared__ int s[SCAN_B];
    int tid = threadIdx.x;
    int base = blockIdx.x * SCAN_TILE + tid * SCAN_ITEMS;
    int local[SCAN_ITEMS];
    int tsum = 0;
#pragma unroll
    for (int q = 0; q < SCAN_ITEMS; q++) {
        int idx = base + q;
        local[q] = (idx < NKEYS) ? g_counts[idx] : 0;
        tsum += local[q];
    }
    s[tid] = tsum;
    __syncthreads();
    for (int off = 1; off < SCAN_B; off <<= 1) {
        int v = 0;
        if (tid >= off) v = s[tid - off];
        __syncthreads();
        s[tid] += v;
        __syncthreads();
    }
    int run = s[tid] - tsum;
#pragma unroll
    for (int q = 0; q < SCAN_ITEMS; q++) {
        int idx = base + q;
        if (idx < NKEYS) g_offsets[idx] = run;
        run += local[q];
    }
    if (tid == SCAN_B - 1) g_partials[blockIdx.x] = s[tid];
}

__global__ void k_scan2() {
    __shared__ int s[128];
    int tid = threadIdx.x;
    int v = (tid < SCAN_NBLK) ? g_partials[tid] : 0;
    s[tid] = v;
    __syncthreads();
    for (int off = 1; off < 128; off <<= 1) {
        int u = 0;
        if (tid >= off) u = s[tid - off];
        __syncthreads();
        s[tid] += u;
        __syncthreads();
    }
    if (tid < SCAN_NBLK) g_partials[tid] = s[tid] - v;
}

__global__ void k_scan3() {
    int add = g_partials[blockIdx.x];
    int base = blockIdx.x * SCAN_TILE;
#pragma unroll
    for (int q = 0; q < SCAN_ITEMS; q++) {
        int idx = base + threadIdx.x + q * SCAN_B;
        if (idx < NKEYS) {
            int v = g_offsets[idx] + add;
            g_offsets[idx] = v;
            g_cursor[idx] = v;
        }
    }
}

__global__ void k_fill(const int* __restrict__ esrc, const int* __restrict__ edst) {
    int i = blockIdx.x * blockDim.x + threadIdx.x;
    if (i >= NEDGE) return;
    int r = i / E_PER;
    int key = r * N_NODES + edst[i];
    int pos = atomicAdd(&g_cursor[key], 1);
    g_csr_src[pos] = esrc[i];
}

// ---------------- M_b accumulation (warp per node; hoisted key loads) --------
// Identical structure/numerics to the 151.0us R12 version; the only change is
// that the 8 (cnt,start) key-pair loads are batched upfront for MLP.
__global__ void k_edge(const float* __restrict__ coeff) {
    int w = (blockIdx.x * blockDim.x + threadIdx.x) >> 5;
    int lane = threadIdx.x & 31;
    if (w >= N_NODES) return;

    int cnts[R], starts[R];
#pragma unroll
    for (int r = 0; r < R; r++) {
        int key = r * N_NODES + w;
        cnts[r]   = g_counts[key];
        starts[r] = g_offsets[key];
    }

    float4 macc[NB];
#pragma unroll
    for (int b = 0; b < NB; b++) macc[b] = make_float4(0.f, 0.f, 0.f, 0.f);

    for (int r = 0; r < R; r++) {
        int start = starts[r];
        int cnt = cnts[r];
        float4 ms = make_float4(0.f, 0.f, 0.f, 0.f);
        for (int e = 0; e < cnt; e++) {
            int s = g_csr_src[start + e];
            uint2 u = ((const uint2*)(g_Af + (size_t)s * KDIM + 512))[lane];
            float2 f01 = __half22float2(*reinterpret_cast<__half2*>(&u.x));
            float2 f23 = __half22float2(*reinterpret_cast<__half2*>(&u.y));
            ms.x += f01.x; ms.y += f01.y; ms.z += f23.x; ms.w += f23.y;
        }
        float inv = 1.0f / fmaxf((float)cnt, 1.0f);
#pragma unroll
        for (int b = 0; b < NB; b++) {
            float c = coeff[r * NB + b] * inv;
            macc[b].x += c * ms.x;
            macc[b].y += c * ms.y;
            macc[b].z += c * ms.z;
            macc[b].w += c * ms.w;
        }
    }
#pragma unroll
    for (int b = 0; b < NB; b++)
        store_h4(macc[b], g_Af + (size_t)w * KDIM + b * D + lane * 4);
}

// ---------------- mma.sync GEMM + fused bias/ReLU/logits epilogue ------------
// CTA: 128x128, 512 threads, 16 warps (4x4), warp tile 32x32.
// BK=64 per stage, double-buffered cp.async.
// D = A*B (both single fp16). __launch_bounds__(512,2) for 2-CTA co-residency.
#define BK 64
#define NSTAGE 10                 // KDIM / BK
#define SAS 144                   // smem row stride bytes (128B data + 16B pad)
#define TILE_B (128 * SAS)        // 18432 per matrix
#define OFF_A  0
#define OFF_B  (1 * TILE_B)
#define STAGE_B (2 * TILE_B)      // 36864
#define OFF_WC   (2 * STAGE_B)    // 73728
#define OFF_BIAS (OFF_WC + 8192)
#define OFF_BCLS (OFF_BIAS + 512)
#define SM_TOTAL (OFF_BCLS + 128) // 82560 (staging 128x132 f32 reuses tile area)
#define STG_STRIDE 132

__global__ void __launch_bounds__(512, 2) k_gemm_mma(const float* __restrict__ W_cls,
                                                     const float* __restrict__ b_cls,
                                                     float* __restrict__ out) {
    extern __shared__ char smem[];
    uint32_t sb = smem_u32(smem);
    int tid = threadIdx.x;
    int lane = tid & 31, wid = tid >> 5;
    int wm = wid & 3, wn = wid >> 2;          // warp tile at (wm*32, wn*32)
    int n0 = blockIdx.x * 128;

    float* sWc   = (float*)(smem + OFF_WC);
    float* sBias = (float*)(smem + OFF_BIAS);
    float* sBcls = (float*)(smem + OFF_BCLS);
    for (int i = tid; i < D * OUT; i += 512) sWc[i] = W_cls[i];
    if (tid < D)   sBias[tid] = g_biasH[tid];
    if (tid < OUT) sBcls[tid] = b_cls[tid];

    float acc[2][4][4];
#pragma unroll
    for (int mt = 0; mt < 2; mt++)
#pragma unroll
        for (int nt = 0; nt < 4; nt++)
#pragma unroll
            for (int q = 0; q < 4; q++) acc[mt][nt][q] = 0.f;

    // 512 threads: 2 x 16B chunks per matrix per thread per stage (BK=64 = 128B/row).
    auto load_stage = [&](int s) {
        uint32_t sm0 = sb + (s & 1) * STAGE_B;
        int k0 = s * BK;
        int row = tid >> 2, kc = tid & 3;     // 128 rows x 4 chunk-pairs
        uint32_t soff = row * SAS + kc * 16;
        size_t aoff = (size_t)(n0 + row) * KDIM + k0 + kc * 8;
        size_t boff = (size_t)row * KDIM + k0 + kc * 8;
        CP_ASYNC16(sm0 + OFF_A + soff,      g_Af + aoff);
        CP_ASYNC16(sm0 + OFF_A + soff + 64, g_Af + aoff + 32);
        CP_ASYNC16(sm0 + OFF_B + soff,      g_Bf + boff);
        CP_ASYNC16(sm0 + OFF_B + soff + 64, g_Bf + boff + 32);
    };

    load_stage(0); CP_COMMIT();

    for (int s = 0; s < NSTAGE; s++) {
        if (s + 1 < NSTAGE) {
            load_stage(s + 1); CP_COMMIT();
            CP_WAIT(1);
        } else {
            CP_WAIT(0);
        }
        __syncthreads();

        uint32_t base = sb + (s & 1) * STAGE_B;
#pragma unroll
        for (int ks = 0; ks < 4; ks++) {
            uint32_t a[2][4], b[4][2];
#pragma unroll
            for (int mt = 0; mt < 2; mt++) {
                uint32_t ro = (uint32_t)(wm * 32 + mt * 16 + (lane & 15)) * SAS
                              + ks * 32 + ((lane >> 4) << 4);
                LDSM4(a[mt], base + OFF_A + ro);
            }
#pragma unroll
            for (int ntp = 0; ntp < 2; ntp++) {
                uint32_t ro = (uint32_t)(wn * 32 + ntp * 16 + ((lane >> 4) << 3) + (lane & 7)) * SAS
                              + ks * 32 + (((lane >> 3) & 1) << 4);
                uint32_t t[4];
                LDSM4(t, base + OFF_B + ro);
                b[2 * ntp][0] = t[0]; b[2 * ntp][1] = t[1];
                b[2 * ntp + 1][0] = t[2]; b[2 * ntp + 1][1] = t[3];
            }
#pragma unroll
            for (int mt = 0; mt < 2; mt++)
#pragma unroll
                for (int nt = 0; nt < 4; nt++)
                    MMA16816F16(acc[mt][nt], a[mt], b[nt]);
        }
        __syncthreads();
    }

    // -------- epilogue: bias + relu into staging smem --------
    float* stg = (float*)smem;                 // 128 x 132, reuses tile area
#pragma unroll
    for (int mt = 0; mt < 2; mt++) {
        int rl0 = wm * 32 + mt * 16 + (lane >> 2);
#pragma unroll
        for (int nt = 0; nt < 4; nt++) {
            int col0 = wn * 32 + nt * 8 + (lane & 3) * 2;
            stg[(rl0)     * STG_STRIDE + col0    ] = fmaxf(acc[mt][nt][0] + sBias[col0],     0.f);
            stg[(rl0)     * STG_STRIDE + col0 + 1] = fmaxf(acc[mt][nt][1] + sBias[col0 + 1], 0.f);
            stg[(rl0 + 8) * STG_STRIDE + col0    ] = fmaxf(acc[mt][nt][2] + sBias[col0],     0.f);
            stg[(rl0 + 8) * STG_STRIDE + col0 + 1] = fmaxf(acc[mt][nt][3] + sBias[col0 + 1], 0.f);
        }
    }
    __syncthreads();

    // -------- per-row: store h + compute logits --------
    if (tid < 128) {
        int node = n0 + tid;
        if (node < N_NODES) {
            float a[OUT];
#pragma unroll
            for (int o = 0; o < OUT; o++) a[o] = sBcls[o];
            const float4* row = (const float4*)(stg + tid * STG_STRIDE);
            float* hptr = out + (size_t)N_NODES * OUT + (size_t)node * D;
#pragma unroll
            for (int q = 0; q < 32; q++) {
                float4 v = row[q];
                const float* w0 = sWc + (q * 4) * OUT;
#pragma unroll
                for (int o = 0; o < OUT; o++)
                    a[o] += v.x * w0[o] + v.y * w0[OUT + o]
                          + v.z * w0[2 * OUT + o] + v.w * w0[3 * OUT + o];
                ((float4*)hptr)[q] = v;
            }
            float* lptr = out + (size_t)node * OUT;
#pragma unroll
            for (int q = 0; q < 4; q++) {
                float4 v;
                v.x = a[q * 4]; v.y = a[q * 4 + 1]; v.z = a[q * 4 + 2]; v.w = a[q * 4 + 3];
                ((float4*)lptr)[q] = v;
            }
        }
    }
}

// ---------------- launch (fork-join: gather/prepB overlap the CSR chain) -----
extern "C" void kernel_launch(void* const* d_in, const int* in_sizes, int n_in,
                              void* d_out, int out_size) {
    const int*   feat_codes = (const int*)d_in[0];
    const int*   nid        = (const int*)d_in[1];
    const int*   esrc       = (const int*)d_in[2];
    const int*   edst       = (const int*)d_in[3];
    const float* emb        = (const float*)d_in[4];
    const float* basis      = (const float*)d_in[5];
    const float* coeff      = (const float*)d_in[6];
    const float* W_self     = (const float*)d_in[7];
    const float* b_rel      = (const float*)d_in[8];
    const float* h_bias     = (const float*)d_in[9];
    const float* W_cls      = (const float*)d_in[10];
    const float* b_cls      = (const float*)d_in[11];
    float* out = (float*)d_out;

    static cudaStream_t s2 = nullptr;
    static cudaEvent_t evFork = nullptr, evJoin = nullptr;
    if (s2 == nullptr) {
        cudaFuncSetAttribute(k_gemm_mma, cudaFuncAttributeMaxDynamicSharedMemorySize, SM_TOTAL);
        cudaStreamCreateWithFlags(&s2, cudaStreamNonBlocking);
        cudaEventCreateWithFlags(&evFork, cudaEventDisableTiming);
        cudaEventCreateWithFlags(&evJoin, cudaEventDisableTiming);
    }

    // fork: side stream runs gather_x + prepB concurrently with the CSR chain
    cudaEventRecord(evFork, 0);
    cudaStreamWaitEvent(s2, evFork, 0);
    k_gather_x<<<(N_NODES + 7) / 8, 256, 0, s2>>>(feat_codes, nid, emb);
    k_prepB<<<(D * KDIM + 255) / 256, 256, 0, s2>>>(basis, W_self, b_rel, h_bias);
    cudaEventRecord(evJoin, s2);

    // main (capture) stream: CSR build
    k_zero<<<(NKEYS + 1023) / 1024, 1024>>>();
    k_count<<<(NEDGE + 255) / 256, 256>>>(edst);
    k_scan1<<<SCAN_NBLK, SCAN_B>>>();
    k_scan2<<<1, 128>>>();
    k_scan3<<<SCAN_NBLK, SCAN_B>>>();
    k_fill<<<(NEDGE + 255) / 256, 256>>>(esrc, edst);

    // join: edge gather needs both branches
    cudaStreamWaitEvent(0, evJoin, 0);
    k_edge<<<(N_NODES + 7) / 8, 256>>>(coeff);
    k_gemm_mma<<<N_PAD / 128, 512, SM_TOTAL>>>(W_cls, b_cls, out);
}

// round 15
// speedup vs baseline: 1.2926x; 1.0461x over previous
#include <cuda_runtime.h>
#include <cuda_fp16.h>
#include <cstdint>

#define N_NODES 50000
#define N_PAD   50048            // 391 * 128
#define D 128
#define R 8
#define E_PER 80000
#define NB 4
#define NF 4
#define V 1000
#define OUT 16
#define NKEYS (R * N_NODES)      // 400000
#define NEDGE (R * E_PER)        // 640000
#define KDIM 640                 // 4*128 (M_b) + 128 (x)

#define SCAN_B 1024
#define SCAN_ITEMS 4
#define SCAN_TILE (SCAN_B * SCAN_ITEMS)
#define SCAN_NBLK ((NKEYS + SCAN_TILE - 1) / SCAN_TILE)   // 98

// ---------------- scratch (device globals; no allocation allowed) ----------
__device__ __align__(16) __half g_Af[(size_t)N_PAD * KDIM];   // A, single fp16
__device__ __align__(16) __half g_Bf[D * KDIM];               // B^T, single fp16
__device__ int   g_counts[NKEYS];
__device__ int   g_offsets[NKEYS];
__device__ int   g_cursor[NKEYS];
__device__ int   g_partials[128];
__device__ int   g_csr_src[NEDGE];
__device__ float g_biasH[D];

// ======================= PTX helpers (sm_80+ features only) =================
__device__ __forceinline__ uint32_t smem_u32(const void* p) {
    uint32_t a;
    asm("{ .reg .u64 t; cvta.to.shared.u64 t, %1; cvt.u32.u64 %0, t; }" : "=r"(a) : "l"(p));
    return a;
}
#define CP_ASYNC16(saddr, gaddr) \
    asm volatile("cp.async.cg.shared.global [%0], [%1], 16;" :: "r"(saddr), "l"(gaddr))
#define CP_COMMIT() asm volatile("cp.async.commit_group;" ::: "memory")
#define CP_WAIT(n)  asm volatile("cp.async.wait_group %0;" :: "n"(n) : "memory")

#define LDSM4(r, addr) \
    asm volatile("ldmatrix.sync.aligned.m8n8.x4.shared.b16 {%0,%1,%2,%3}, [%4];" \
        : "=r"((r)[0]), "=r"((r)[1]), "=r"((r)[2]), "=r"((r)[3]) : "r"(addr))

#define MMA16816F16(c, a, b) \
    asm volatile("mma.sync.aligned.m16n8k16.row.col.f32.f16.f16.f32 " \
        "{%0,%1,%2,%3}, {%4,%5,%6,%7}, {%8,%9}, {%0,%1,%2,%3};" \
        : "+f"((c)[0]), "+f"((c)[1]), "+f"((c)[2]), "+f"((c)[3]) \
        : "r"((a)[0]), "r"((a)[1]), "r"((a)[2]), "r"((a)[3]), \
          "r"((b)[0]), "r"((b)[1]))

// write float4 as 4 fp16 (8B packed store)
__device__ __forceinline__ void store_h4(float4 v, __half* p) {
    __half2 a = __floats2half2_rn(v.x, v.y);
    __half2 b = __floats2half2_rn(v.z, v.w);
    uint2 u;
    u.x = *reinterpret_cast<unsigned*>(&a);
    u.y = *reinterpret_cast<unsigned*>(&b);
    *reinterpret_cast<uint2*>(p) = u;
}

// ---------------- zero counts ----------------------------------------------
__global__ void k_zero() {
    int i = blockIdx.x * blockDim.x + threadIdx.x;
    if (i < NKEYS) g_counts[i] = 0;
}

// ---------------- x = sum_f emb[f, codes[f, nid[n]]]  (fp16 into A) ---------
__global__ void k_gather_x(const int* __restrict__ fc, const int* __restrict__ nid,
                           const float* __restrict__ emb) {
    int w = (blockIdx.x * blockDim.x + threadIdx.x) >> 5;
    int lane = threadIdx.x & 31;
    if (w >= N_NODES) return;
    int node = nid[w];
    float4 acc = make_float4(0.f, 0.f, 0.f, 0.f);
#pragma unroll
    for (int f = 0; f < NF; f++) {
        int code = fc[f * N_NODES + node];
        const float4* src = (const float4*)(emb + ((size_t)f * V + code) * D);
        float4 v = src[lane];
        acc.x += v.x; acc.y += v.y; acc.z += v.z; acc.w += v.w;
    }
    store_h4(acc, g_Af + (size_t)w * KDIM + 512 + lane * 4);
}

// ---------------- B^T fp16 + biasH -------------------------------------------
__global__ void k_prepB(const float* __restrict__ basis, const float* __restrict__ W_self,
                        const float* __restrict__ b_rel, const float* __restrict__ h_bias) {
    int idx = blockIdx.x * blockDim.x + threadIdx.x;
    if (idx < D) {
        float s = h_bias[idx];
#pragma unroll
        for (int r = 0; r < R; r++) s += b_rel[r * D + idx];
        g_biasH[idx] = s;
    }
    if (idx >= D * KDIM) return;
    int n = idx / KDIM;
    int k = idx % KDIM;
    float v;
    if (k < 512) {
        v = basis[(size_t)((k >> 7) * D + (k & 127)) * D + n];
    } else {
        v = 0.f;
#pragma unroll
        for (int r = 0; r < R; r++) v += W_self[(size_t)(r * D + (k - 512)) * D + n];
    }
    g_Bf[idx] = __float2half_rn(v);
}

// ---------------- CSR build: count -> scan (scan1 + fused scan3) -> fill -----
__global__ void k_count(const int* __restrict__ edst) {
    int i = blockIdx.x * blockDim.x + threadIdx.x;
    if (i >= NEDGE) return;
    int r = i / E_PER;
    atomicAdd(&g_counts[r * N_NODES + edst[i]], 1);
}

__global__ void k_scan1() {
    __shared__ int s[SCAN_B];
    int tid = threadIdx.x;
    int base = blockIdx.x * SCAN_TILE + tid * SCAN_ITEMS;
    int local[SCAN_ITEMS];
    int tsum = 0;
#pragma unroll
    for (int q = 0; q < SCAN_ITEMS; q++) {
        int idx = base + q;
        local[q] = (idx < NKEYS) ? g_counts[idx] : 0;
        tsum += local[q];
    }
    s[tid] = tsum;
    __syncthreads();
    for (int off = 1; off < SCAN_B; off <<= 1) {
        int v = 0;
        if (tid >= off) v = s[tid - off];
        __syncthreads();
        s[tid] += v;
        __syncthreads();
    }
    int run = s[tid] - tsum;
#pragma unroll
    for (int q = 0; q < SCAN_ITEMS; q++) {
        int idx = base + q;
        if (idx < NKEYS) g_offsets[idx] = run;
        run += local[q];
    }
    if (tid == SCAN_B - 1) g_partials[blockIdx.x] = s[tid];
}

// scan3: each block redundantly reduces the preceding blocks' partials
// (<=98 values, one 128-wide smem tree) — replaces the separate k_scan2 kernel.
// Offsets are integer-exact, identical to the two-kernel version.
__global__ void k_scan3() {
    __shared__ int sp[128];
    int tid = threadIdx.x;
    if (tid < 128) sp[tid] = (tid < (int)blockIdx.x && tid < SCAN_NBLK) ? g_partials[tid] : 0;
    __syncthreads();
#pragma unroll
    for (int off = 64; off > 0; off >>= 1) {
        if (tid < off) sp[tid] += sp[tid + off];
        __syncthreads();
    }
    int add = sp[0];
    int base = blockIdx.x * SCAN_TILE;
#pragma unroll
    for (int q = 0; q < SCAN_ITEMS; q++) {
        int idx = base + tid + q * SCAN_B;
        if (idx < NKEYS) {
            int v = g_offsets[idx] + add;
            g_offsets[idx] = v;
            g_cursor[idx] = v;
        }
    }
}

__global__ void k_fill(const int* __restrict__ esrc, const int* __restrict__ edst) {
    int i = blockIdx.x * blockDim.x + threadIdx.x;
    if (i >= NEDGE) return;
    int r = i / E_PER;
    int key = r * N_NODES + edst[i];
    int pos = atomicAdd(&g_cursor[key], 1);
    g_csr_src[pos] = esrc[i];
}

// ---------------- M_b accumulation (warp per node; exact R12 form) -----------
__global__ void k_edge(const float* __restrict__ coeff) {
    int w = (blockIdx.x * blockDim.x + threadIdx.x) >> 5;
    int lane = threadIdx.x & 31;
    if (w >= N_NODES) return;

    float4 macc[NB];
#pragma unroll
    for (int b = 0; b < NB; b++) macc[b] = make_float4(0.f, 0.f, 0.f, 0.f);

    for (int r = 0; r < R; r++) {
        int key = r * N_NODES + w;
        int start = g_offsets[key];
        int cnt = g_counts[key];
        float4 ms = make_float4(0.f, 0.f, 0.f, 0.f);
        for (int e = 0; e < cnt; e++) {
            int s = g_csr_src[start + e];
            // x lives (fp16) in the A matrix's tail slice: g_Af[s*KDIM + 512 ..]
            uint2 u = ((const uint2*)(g_Af + (size_t)s * KDIM + 512))[lane];
            float2 f01 = __half22float2(*reinterpret_cast<__half2*>(&u.x));
            float2 f23 = __half22float2(*reinterpret_cast<__half2*>(&u.y));
            ms.x += f01.x; ms.y += f01.y; ms.z += f23.x; ms.w += f23.y;
        }
        float inv = 1.0f / fmaxf((float)cnt, 1.0f);
#pragma unroll
        for (int b = 0; b < NB; b++) {
            float c = coeff[r * NB + b] * inv;
            macc[b].x += c * ms.x;
            macc[b].y += c * ms.y;
            macc[b].z += c * ms.z;
            macc[b].w += c * ms.w;
        }
    }
#pragma unroll
    for (int b = 0; b < NB; b++)
        store_h4(macc[b], g_Af + (size_t)w * KDIM + b * D + lane * 4);
}

// ---------------- mma.sync GEMM + fused bias/ReLU/logits epilogue ------------
// CTA: 128x128, 512 threads, 16 warps (4x4), warp tile 32x32.
// BK=64 per stage, double-buffered cp.async.
// D = A*B (both single fp16). __launch_bounds__(512,2) for 2-CTA co-residency.
#define BK 64
#define NSTAGE 10                 // KDIM / BK
#define SAS 144                   // smem row stride bytes (128B data + 16B pad)
#define TILE_B (128 * SAS)        // 18432 per matrix
#define OFF_A  0
#define OFF_B  (1 * TILE_B)
#define STAGE_B (2 * TILE_B)      // 36864
#define OFF_WC   (2 * STAGE_B)    // 73728
#define OFF_BIAS (OFF_WC + 8192)
#define OFF_BCLS (OFF_BIAS + 512)
#define SM_TOTAL (OFF_BCLS + 128) // 82560 (staging 128x132 f32 reuses tile area)
#define STG_STRIDE 132

__global__ void __launch_bounds__(512, 2) k_gemm_mma(const float* __restrict__ W_cls,
                                                     const float* __restrict__ b_cls,
                                                     float* __restrict__ out) {
    extern __shared__ char smem[];
    uint32_t sb = smem_u32(smem);
    int tid = threadIdx.x;
    int lane = tid & 31, wid = tid >> 5;
    int wm = wid & 3, wn = wid >> 2;          // warp tile at (wm*32, wn*32)
    int n0 = blockIdx.x * 128;

    float* sWc   = (float*)(smem + OFF_WC);
    float* sBias = (float*)(smem + OFF_BIAS);
    float* sBcls = (float*)(smem + OFF_BCLS);
    for (int i = tid; i < D * OUT; i += 512) sWc[i] = W_cls[i];
    if (tid < D)   sBias[tid] = g_biasH[tid];
    if (tid < OUT) sBcls[tid] = b_cls[tid];

    float acc[2][4][4];
#pragma unroll
    for (int mt = 0; mt < 2; mt++)
#pragma unroll
        for (int nt = 0; nt < 4; nt++)
#pragma unroll
            for (int q = 0; q < 4; q++) acc[mt][nt][q] = 0.f;

    // 512 threads: 2 x 16B chunks per matrix per thread per stage (BK=64 = 128B/row).
    auto load_stage = [&](int s) {
        uint32_t sm0 = sb + (s & 1) * STAGE_B;
        int k0 = s * BK;
        int row = tid >> 2, kc = tid & 3;     // 128 rows x 4 chunk-pairs
        uint32_t soff = row * SAS + kc * 16;
        size_t aoff = (size_t)(n0 + row) * KDIM + k0 + kc * 8;
        size_t boff = (size_t)row * KDIM + k0 + kc * 8;
        CP_ASYNC16(sm0 + OFF_A + soff,      g_Af + aoff);
        CP_ASYNC16(sm0 + OFF_A + soff + 64, g_Af + aoff + 32);
        CP_ASYNC16(sm0 + OFF_B + soff,      g_Bf + boff);
        CP_ASYNC16(sm0 + OFF_B + soff + 64, g_Bf + boff + 32);
    };

    load_stage(0); CP_COMMIT();

    for (int s = 0; s < NSTAGE; s++) {
        if (s + 1 < NSTAGE) {
            load_stage(s + 1); CP_COMMIT();
            CP_WAIT(1);
        } else {
            CP_WAIT(0);
        }
        __syncthreads();

        uint32_t base = sb + (s & 1) * STAGE_B;
#pragma unroll
        for (int ks = 0; ks < 4; ks++) {
            uint32_t a[2][4], b[4][2];
#pragma unroll
            for (int mt = 0; mt < 2; mt++) {
                uint32_t ro = (uint32_t)(wm * 32 + mt * 16 + (lane & 15)) * SAS
                              + ks * 32 + ((lane >> 4) << 4);
                LDSM4(a[mt], base + OFF_A + ro);
            }
#pragma unroll
            for (int ntp = 0; ntp < 2; ntp++) {
                uint32_t ro = (uint32_t)(wn * 32 + ntp * 16 + ((lane >> 4) << 3) + (lane & 7)) * SAS
                              + ks * 32 + (((lane >> 3) & 1) << 4);
                uint32_t t[4];
                LDSM4(t, base + OFF_B + ro);
                b[2 * ntp][0] = t[0]; b[2 * ntp][1] = t[1];
                b[2 * ntp + 1][0] = t[2]; b[2 * ntp + 1][1] = t[3];
            }
#pragma unroll
            for (int mt = 0; mt < 2; mt++)
#pragma unroll
                for (int nt = 0; nt < 4; nt++)
                    MMA16816F16(acc[mt][nt], a[mt], b[nt]);
        }
        __syncthreads();
    }

    // -------- epilogue: bias + relu into staging smem --------
    float* stg = (float*)smem;                 // 128 x 132, reuses tile area
#pragma unroll
    for (int mt = 0; mt < 2; mt++) {
        int rl0 = wm * 32 + mt * 16 + (lane >> 2);
#pragma unroll
        for (int nt = 0; nt < 4; nt++) {
            int col0 = wn * 32 + nt * 8 + (lane & 3) * 2;
            stg[(rl0)     * STG_STRIDE + col0    ] = fmaxf(acc[mt][nt][0] + sBias[col0],     0.f);
            stg[(rl0)     * STG_STRIDE + col0 + 1] = fmaxf(acc[mt][nt][1] + sBias[col0 + 1], 0.f);
            stg[(rl0 + 8) * STG_STRIDE + col0    ] = fmaxf(acc[mt][nt][2] + sBias[col0],     0.f);
            stg[(rl0 + 8) * STG_STRIDE + col0 + 1] = fmaxf(acc[mt][nt][3] + sBias[col0 + 1], 0.f);
        }
    }
    __syncthreads();

    // -------- per-row: store h + compute logits --------
    if (tid < 128) {
        int node = n0 + tid;
        if (node < N_NODES) {
            float a[OUT];
#pragma unroll
            for (int o = 0; o < OUT; o++) a[o] = sBcls[o];
            const float4* row = (const float4*)(stg + tid * STG_STRIDE);
            float* hptr = out + (size_t)N_NODES * OUT + (size_t)node * D;
#pragma unroll
            for (int q = 0; q < 32; q++) {
                float4 v = row[q];
                const float* w0 = sWc + (q * 4) * OUT;
#pragma unroll
                for (int o = 0; o < OUT; o++)
                    a[o] += v.x * w0[o] + v.y * w0[OUT + o]
                          + v.z * w0[2 * OUT + o] + v.w * w0[3 * OUT + o];
                ((float4*)hptr)[q] = v;
            }
            float* lptr = out + (size_t)node * OUT;
#pragma unroll
            for (int q = 0; q < 4; q++) {
                float4 v;
                v.x = a[q * 4]; v.y = a[q * 4 + 1]; v.z = a[q * 4 + 2]; v.w = a[q * 4 + 3];
                ((float4*)lptr)[q] = v;
            }
        }
    }
}

// ---------------- launch (fork-join: gather/prepB overlap the CSR chain) -----
extern "C" void kernel_launch(void* const* d_in, const int* in_sizes, int n_in,
                              void* d_out, int out_size) {
    const int*   feat_codes = (const int*)d_in[0];
    const int*   nid        = (const int*)d_in[1];
    const int*   esrc       = (const int*)d_in[2];
    const int*   edst       = (const int*)d_in[3];
    const float* emb        = (const float*)d_in[4];
    const float* basis      = (const float*)d_in[5];
    const float* coeff      = (const float*)d_in[6];
    const float* W_self     = (const float*)d_in[7];
    const float* b_rel      = (const float*)d_in[8];
    const float* h_bias     = (const float*)d_in[9];
    const float* W_cls      = (const float*)d_in[10];
    const float* b_cls      = (const float*)d_in[11];
    float* out = (float*)d_out;

    static cudaStream_t s2 = nullptr;
    static cudaEvent_t evFork = nullptr, evJoin = nullptr;
    if (s2 == nullptr) {
        cudaFuncSetAttribute(k_gemm_mma, cudaFuncAttributeMaxDynamicSharedMemorySize, SM_TOTAL);
        cudaStreamCreateWithFlags(&s2, cudaStreamNonBlocking);
        cudaEventCreateWithFlags(&evFork, cudaEventDisableTiming);
        cudaEventCreateWithFlags(&evJoin, cudaEventDisableTiming);
    }

    // fork: side stream runs gather_x + prepB concurrently with the CSR chain
    cudaEventRecord(evFork, 0);
    cudaStreamWaitEvent(s2, evFork, 0);
    k_gather_x<<<(N_NODES + 7) / 8, 256, 0, s2>>>(feat_codes, nid, emb);
    k_prepB<<<(D * KDIM + 255) / 256, 256, 0, s2>>>(basis, W_self, b_rel, h_bias);
    cudaEventRecord(evJoin, s2);

    // main (capture) stream: CSR build
    k_zero<<<(NKEYS + 1023) / 1024, 1024>>>();
    k_count<<<(NEDGE + 255) / 256, 256>>>(edst);
    k_scan1<<<SCAN_NBLK, SCAN_B>>>();
    k_scan3<<<SCAN_NBLK, SCAN_B>>>();
    k_fill<<<(NEDGE + 255) / 256, 256>>>(esrc, edst);

    // join: edge gather needs both branches
    cudaStreamWaitEvent(0, evJoin, 0);
    k_edge<<<(N_NODES + 7) / 8, 256>>>(coeff);
    k_gemm_mma<<<N_PAD / 128, 512, SM_TOTAL>>>(W_cls, b_cls, out);
}